// round 7
// baseline (speedup 1.0000x reference)
#include <cuda_runtime.h>
#include <math.h>

// Fixed shapes:
//   images   [8, 3, 512, 512] f32
//   kernels  [8, 9, 256, 256] f32
//   offsets_x[8, 9, 256, 256] f32
//   offsets_y[8, 9, 256, 256] f32
//   output   [8, 256, 256, 3] f32
#define HWQ   65536      // 256*256 (one offset plane)
#define IMGP  262144     // 512*512 (one image channel plane)

// Duplicated-pair patch: element (ch,r,c) = (im[xb+r][xb+c], im[xb+r][xb+c+1]).
// 35 rows x 36 cols (cols 0..34 used, col 35 = pad/fill-safe) per channel.
// Row stride 36 float2 -> lane address multiplier 37 === 5 (mod 16): bijective
// per half-warp -> conflict-free LDS.64 on the diagonal gather pattern.
#define P_STR2  36
#define P_CH2   1260               // 35 * 36 float2 per channel
#define P_ELEMS (3 * P_CH2)        // 3780 float2 = 30240 B

// One tap for one output pixel. Corners come from the float2 patch as three
// row-pair quads per channel (A=.x of row r0, B=.y of row r0, C/D from r0+1).
// Channel mixing replicates the reference's scrambled m2 reshape.
__device__ __forceinline__ void tap_accum(
    float oxo, float oyo, float kw,
    const float2* __restrict__ patch,   // smem patch base (channel 0)
    float kxf, float kyf, float uj, int xboff,
    float a0, float a1, float b0, float b1,
    float& acc0, float& acc1, float& acc2)
{
    // coords = ((off + 1.5) + k*) + u[j]   (exact reference association order)
    float xc = ((oxo + 1.5f) + kxf) + uj;
    float yc = ((oyo + 1.5f) + kyf) + uj;
    float flx = floorf(xc);
    float fly = floorf(yc);
    // Single combined patch index: (x0-xb)*36 + (y0-xb); exact in fp32 (<2^24).
    int idx = __float2int_rz(fmaf(flx, 36.0f, fly)) - xboff;

    const float2* p = patch + idx;
    float2 ab0 = p[0],          cd0 = p[P_STR2];            // ch0: (A0,B0),(C0,D0)
    float2 ab1 = p[P_CH2],      cd1 = p[P_CH2 + P_STR2];    // ch1
    float2 ab2 = p[2 * P_CH2],  cd2 = p[2 * P_CH2 + P_STR2];// ch2

    float kb0 = kw * b0, kb1 = kw * b1;
    float w00 = kb0 * a0, w01 = kb0 * a1;
    float w10 = kb1 * a0, w11 = kb1 * a1;

    // acc0 += w00*B0 + w01*C0 + w10*D1 + w11*A2
    // acc1 += w00*A0 + w01*B1 + w10*C1 + w11*D2
    // acc2 += w00*D0 + w01*A1 + w10*B2 + w11*C2
    acc0 = fmaf(w00, ab0.y, fmaf(w01, cd0.x, fmaf(w10, cd1.y, fmaf(w11, ab2.x, acc0))));
    acc1 = fmaf(w00, ab0.x, fmaf(w01, ab1.y, fmaf(w10, cd1.x, fmaf(w11, cd2.y, acc1))));
    acc2 = fmaf(w00, cd0.y, fmaf(w01, ab1.x, fmaf(w10, ab2.y, fmaf(w11, cd2.x, acc2))));
}

__device__ __forceinline__ float softround255(float o)
{
    float v = o * 255.0f;
    float r = v - rintf(v);   // exact-period reduction (robust under fast-math)
    return v - sinf(6.2831855f * r) * 0.15915494f;
}

// Block = 256 threads = 32 columns x 8 row-pairs.
// Each thread computes BOTH output pixels (b, i, j) and (b, i+128, j):
// they share identical weight-source samples (g-side vs f-side), halving
// the weight-offset loads. All image gathers come from the smem patch.
__global__ __launch_bounds__(256, 4)
void Downsampler_74491912782199_kernel(
    const float* __restrict__ images,
    const float* __restrict__ kernels,
    const float* __restrict__ offx,
    const float* __restrict__ offy,
    float* __restrict__ out)
{
    __shared__ float2 patch[P_ELEMS];   // 30240 B

    const int bid = blockIdx.x;               // 1024 blocks
    const int jt  = bid & 7;                  // 8 column tiles of 32
    const int ipt = (bid >> 3) & 15;          // 16 row-pair tiles of 8
    const int b   = bid >> 7;                 // 8 batches

    const int tid = threadIdx.x;
    const int tx  = tid & 31;                 // column within tile
    const int ty  = tid >> 5;                 // row-pair within tile

    const int j0 = jt * 32;
    const int xb = j0 + 2;                    // patch origin (rows == cols)
    const int xboff = xb * (P_STR2 + 1);      // xb*36 + xb

    const float* imb = images + (size_t)b * 3 * IMGP;

    // ---- Cooperative patch fill: 3 x 35 x 36 float2 (overlapping pairs) ----
    for (int e = tid; e < P_ELEMS; e += 256) {
        int ch  = e / P_CH2;
        int rem = e - ch * P_CH2;
        int r   = rem / P_STR2;
        int c   = rem - r * P_STR2;
        const float* s = imb + (size_t)ch * IMGP + (size_t)(xb + r) * 512 + (xb + c);
        patch[e] = make_float2(__ldg(s), __ldg(s + 1));
    }
    __syncthreads();

    const int j    = j0 + tx;
    const int i_lo = ipt * 8 + ty;            // 0..127

    const int m_lo = i_lo * 256 + j;          // plane index of low pixel
    const int m_hi = m_lo + 32768;            // plane index of high pixel (i+128)
    const int q0 = 2 * m_lo;                  // weight-source pixel indices
    const int q1 = q0 + 1;
    const float uq0 = (float)(q0 & 255) + 0.5f;
    const float uq1 = (float)(q1 & 255) + 0.5f;
    const float uj  = (float)j + 0.5f;

    const float* oxb = offx    + (size_t)b * 9 * HWQ;
    const float* oyb = offy    + (size_t)b * 9 * HWQ;
    const float* kwb = kernels + (size_t)b * 9 * HWQ;

    float L0 = 0.f, L1 = 0.f, L2 = 0.f;
    float H0 = 0.f, H1 = 0.f, H2 = 0.f;

#pragma unroll
    for (int k = 0; k < 9; ++k) {
        // weight-source sample positions: s = 18*m' + 2k + {0,1}
        const int t0  = 2 * k;
        const int t1  = 2 * k + 1;
        const int kp0 = (t0 < 9) ? t0 : t0 - 9;
        const int kp1 = (t1 < 9) ? t1 : t1 - 9;
        const int qa0 = (t0 < 9) ? q0 : q1;
        const int qa1 = (t1 < 9) ? q0 : q1;
        const float u0 = (t0 < 9) ? uq0 : uq1;
        const float u1 = (t1 < 9) ? uq0 : uq1;

        float wx0 = __ldg(oxb + kp0 * HWQ + qa0);
        float wx1 = __ldg(oxb + kp1 * HWQ + qa1);
        float wy0 = __ldg(oyb + kp0 * HWQ + qa0);
        float wy1 = __ldg(oyb + kp1 * HWQ + qa1);

        // frac / one-minus-frac of the source coordinates, reference order
        float x, fl;
        x = ((wx0 + 1.5f) + (float)(kp0 / 3)) + u0; fl = floorf(x);
        float ga0 = (fl + 1.0f) - x, fa0 = x - fl;
        x = ((wx1 + 1.5f) + (float)(kp1 / 3)) + u1; fl = floorf(x);
        float ga1 = (fl + 1.0f) - x, fa1 = x - fl;
        x = ((wy0 + 1.5f) + (float)(kp0 % 3)) + u0; fl = floorf(x);
        float gb0 = (fl + 1.0f) - x, fb0 = x - fl;
        x = ((wy1 + 1.5f) + (float)(kp1 % 3)) + u1; fl = floorf(x);
        float gb1 = (fl + 1.0f) - x, fb1 = x - fl;

        const float kxf = (float)(k / 3);
        const float kyf = (float)(k % 3);
        const float* oxk = oxb + k * HWQ;
        const float* oyk = oyb + k * HWQ;
        const float* kwk = kwb + k * HWQ;

        // low pixel (i < 128): g-side weights; high pixel (i >= 128): f-side
        tap_accum(__ldg(oxk + m_lo), __ldg(oyk + m_lo), __ldg(kwk + m_lo),
                  patch, kxf, kyf, uj, xboff, ga0, ga1, gb0, gb1, L0, L1, L2);
        tap_accum(__ldg(oxk + m_hi), __ldg(oyk + m_hi), __ldg(kwk + m_hi),
                  patch, kxf, kyf, uj, xboff, fa0, fa1, fb0, fb1, H0, H1, H2);
    }

    // output layout [B, 256, 256, 3], row-major
    size_t oL = ((size_t)(b * 256 + i_lo) * 256 + j) * 3;
    size_t oH = oL + (size_t)128 * 256 * 3;
    out[oL + 0] = softround255(L0);
    out[oL + 1] = softround255(L1);
    out[oL + 2] = softround255(L2);
    out[oH + 0] = softround255(H0);
    out[oH + 1] = softround255(H1);
    out[oH + 2] = softround255(H2);
}

extern "C" void kernel_launch(void* const* d_in, const int* in_sizes, int n_in,
                              void* d_out, int out_size)
{
    (void)in_sizes; (void)n_in; (void)out_size;
    const float* images  = (const float*)d_in[0];
    const float* kernels = (const float*)d_in[1];
    const float* offx    = (const float*)d_in[2];
    const float* offy    = (const float*)d_in[3];
    float* out = (float*)d_out;

    // 1024 blocks = 8 batches * 16 row-pair tiles * 8 column tiles
    Downsampler_74491912782199_kernel<<<1024, 256>>>(images, kernels, offx, offy, out);
}